// round 13
// baseline (speedup 1.0000x reference)
#include <cuda_runtime.h>
#include <cuda_bf16.h>
#include <stdint.h>

#define EPSQ 1e-5f
#define MTOK 32768
#define DDIM 1024
#define FDIM 3072

// ---------------- scratch (__device__ globals; no allocation) ----------------
__device__ int8_t g_qx[(size_t)MTOK * DDIM];        // 32 MB
__device__ int8_t g_qh[(size_t)MTOK * FDIM];        // 96 MB
__device__ int8_t g_w1[(size_t)FDIM * DDIM];        // 3 MB
__device__ int8_t g_w2[(size_t)DDIM * FDIM];        // 3 MB
__device__ float  g_hidden[(size_t)MTOK * FDIM];    // 384 MB
__device__ float  g_ascale[MTOK];
__device__ float  g_hscale[MTOK];
__device__ float  g_wpart[2048];
__device__ float  g_wmeta[4];  // ws1, fac1, ws2, fac2

// ---------------- ptx helpers (base sm_80+ ISA only) ----------------
__device__ __forceinline__ uint32_t s2u(const void* p) {
    uint32_t a;
    asm("{ .reg .u64 t; cvta.to.shared.u64 t, %1; cvt.u32.u64 %0, t; }" : "=r"(a) : "l"(p));
    return a;
}
__device__ __forceinline__ void cp16(uint32_t saddr, const void* gaddr) {
    asm volatile("cp.async.cg.shared.global [%0], [%1], 16;" :: "r"(saddr), "l"(gaddr) : "memory");
}
__device__ __forceinline__ void ldm_x4(uint32_t* r, uint32_t addr) {
    asm volatile("ldmatrix.sync.aligned.m8n8.x4.shared.b16 {%0,%1,%2,%3}, [%4];"
                 : "=r"(r[0]), "=r"(r[1]), "=r"(r[2]), "=r"(r[3]) : "r"(addr));
}
__device__ __forceinline__ void imma(int* d, const uint32_t* a, const uint32_t* b) {
    asm volatile(
        "mma.sync.aligned.m16n8k32.row.col.s32.s8.s8.s32 "
        "{%0,%1,%2,%3}, {%4,%5,%6,%7}, {%8,%9}, {%0,%1,%2,%3};"
        : "+r"(d[0]), "+r"(d[1]), "+r"(d[2]), "+r"(d[3])
        : "r"(a[0]), "r"(a[1]), "r"(a[2]), "r"(a[3]), "r"(b[0]), "r"(b[1]));
}
__device__ __forceinline__ int dp4a_(int a, int b, int c) {
    int d;
    asm("dp4a.s32.s32 %0, %1, %2, %3;" : "=r"(d) : "r"(a), "r"(b), "r"(c));
    return d;
}
// 16B-chunk swizzle within a 128B smem row (c,r terms 3 bits each)
#define SW(r, c) ((uint32_t)((c) ^ ((r) & 7) ^ (((r) >> 3) & 7)))

// ---------------- activation quantization (x) ----------------
__global__ void k_quant_x(const float* __restrict__ x) {
    int m = blockIdx.x, t = threadIdx.x;  // 256 threads, row of 1024
    const float4* row = (const float4*)(x + (size_t)m * DDIM);
    float4 v = row[t];
    float am = fmaxf(fmaxf(fabsf(v.x), fabsf(v.y)), fmaxf(fabsf(v.z), fabsf(v.w)));
    for (int o = 16; o > 0; o >>= 1) am = fmaxf(am, __shfl_xor_sync(0xffffffffu, am, o));
    __shared__ float red[8];
    __shared__ float s_c;
    if ((t & 31) == 0) red[t >> 5] = am;
    __syncthreads();
    if (t == 0) {
        float c = red[0];
        for (int i = 1; i < 8; i++) c = fmaxf(c, red[i]);
        c = fmaxf(c, EPSQ);
        s_c = c;
        g_ascale[m] = c / 127.0f;
    }
    __syncthreads();
    float scale = 127.0f / s_c;
    char4 q;
    q.x = (signed char)fminf(fmaxf(rintf(v.x * scale), -128.f), 127.f);
    q.y = (signed char)fminf(fmaxf(rintf(v.y * scale), -128.f), 127.f);
    q.z = (signed char)fminf(fmaxf(rintf(v.z * scale), -128.f), 127.f);
    q.w = (signed char)fminf(fmaxf(rintf(v.w * scale), -128.f), 127.f);
    *(char4*)(g_qx + (size_t)m * DDIM + t * 4) = q;
}

// ---------------- weight |w| partial sums ----------------
__global__ void k_wsum(const float* __restrict__ up_w, const float* __restrict__ down_w) {
    int b = blockIdx.x, t = threadIdx.x;
    const float* base = (b < 1024) ? (up_w + (size_t)b * 3072)
                                   : (down_w + (size_t)(b - 1024) * 3072);
    const float4* v4 = (const float4*)base;
    float s = 0.f;
#pragma unroll
    for (int j = 0; j < 3; j++) {
        float4 v = v4[t + j * 256];
        s += fabsf(v.x) + fabsf(v.y) + fabsf(v.z) + fabsf(v.w);
    }
    for (int o = 16; o > 0; o >>= 1) s += __shfl_down_sync(0xffffffffu, s, o);
    __shared__ float red[8];
    if ((t & 31) == 0) red[t >> 5] = s;
    __syncthreads();
    if (t == 0) {
        float tot = 0.f;
        for (int i = 0; i < 8; i++) tot += red[i];
        g_wpart[b] = tot;
    }
}

// ---------------- ternarize (scale computed redundantly per block, fixed order) ----
__global__ void k_ternarize(const float* __restrict__ up_w, const float* __restrict__ down_w) {
    int t = threadIdx.x;  // 256
    float s1 = 0.f, s2 = 0.f;
#pragma unroll
    for (int j = 0; j < 4; j++) {
        s1 += g_wpart[t + j * 256];
        s2 += g_wpart[1024 + t + j * 256];
    }
    for (int o = 16; o > 0; o >>= 1) {
        s1 += __shfl_down_sync(0xffffffffu, s1, o);
        s2 += __shfl_down_sync(0xffffffffu, s2, o);
    }
    __shared__ float r1[8], r2[8];
    __shared__ float sws[2];
    if ((t & 31) == 0) { r1[t >> 5] = s1; r2[t >> 5] = s2; }
    __syncthreads();
    if (t == 0) {
        float t1 = 0.f, t2 = 0.f;
        for (int i = 0; i < 8; i++) { t1 += r1[i]; t2 += r2[i]; }
        float m1 = t1 / (3072.0f * 1024.0f);
        float m2 = t2 / (3072.0f * 1024.0f);
        float f1 = fmaxf(m1, EPSQ), f2 = fmaxf(m2, EPSQ);
        sws[0] = 1.0f / f1;
        sws[1] = 1.0f / f2;
        if (blockIdx.x == 0) {
            g_wmeta[0] = 1.0f / f1; g_wmeta[1] = f1;
            g_wmeta[2] = 1.0f / f2; g_wmeta[3] = f2;
        }
    }
    __syncthreads();

    const size_t half = (size_t)3072 * 1024;
    size_t i = ((size_t)blockIdx.x * 256 + t) * 4;
    const float* src;
    int8_t* dst;
    float ws;
    if (i < half) { src = up_w + i;            dst = g_w1 + i;          ws = sws[0]; }
    else          { src = down_w + (i - half); dst = g_w2 + (i - half); ws = sws[1]; }
    float4 w = *(const float4*)src;
    char4 q;
    q.x = (signed char)fminf(fmaxf(rintf(w.x * ws), -1.f), 1.f);
    q.y = (signed char)fminf(fmaxf(rintf(w.y * ws), -1.f), 1.f);
    q.z = (signed char)fminf(fmaxf(rintf(w.z * ws), -1.f), 1.f);
    q.w = (signed char)fminf(fmaxf(rintf(w.w * ws), -1.f), 1.f);
    *(char4*)dst = q;
}

// ---------------- activation quantization (hidden) ----------------
__global__ void k_quant_h() {
    int m = blockIdx.x, t = threadIdx.x;  // 256 threads, row of 3072
    const float4* row = (const float4*)(g_hidden + (size_t)m * FDIM);
    float4 v[3];
    float am = 0.f;
#pragma unroll
    for (int j = 0; j < 3; j++) {
        v[j] = row[t + j * 256];
        am = fmaxf(am, fmaxf(fmaxf(fabsf(v[j].x), fabsf(v[j].y)),
                             fmaxf(fabsf(v[j].z), fabsf(v[j].w))));
    }
    for (int o = 16; o > 0; o >>= 1) am = fmaxf(am, __shfl_xor_sync(0xffffffffu, am, o));
    __shared__ float red[8];
    __shared__ float s_c;
    if ((t & 31) == 0) red[t >> 5] = am;
    __syncthreads();
    if (t == 0) {
        float c = red[0];
        for (int i = 1; i < 8; i++) c = fmaxf(c, red[i]);
        c = fmaxf(c, EPSQ);
        s_c = c;
        g_hscale[m] = c / 127.0f;
    }
    __syncthreads();
    float scale = 127.0f / s_c;
#pragma unroll
    for (int j = 0; j < 3; j++) {
        char4 q;
        q.x = (signed char)fminf(fmaxf(rintf(v[j].x * scale), -128.f), 127.f);
        q.y = (signed char)fminf(fmaxf(rintf(v[j].y * scale), -128.f), 127.f);
        q.z = (signed char)fminf(fmaxf(rintf(v[j].z * scale), -128.f), 127.f);
        q.w = (signed char)fminf(fmaxf(rintf(v[j].w * scale), -128.f), 127.f);
        *(char4*)(g_qh + (size_t)m * FDIM + (t + j * 256) * 4) = q;
    }
}

// ---------------- hybrid tensor+dp4a int8 GEMM, 128x128 tile ----------------
// 512 threads, 1 CTA/SM. K consumed in 128-byte chunks, 4-stage cp.async ring
// (32KB/stage: A[128][128] + B[128][128]). Warps 0-7: IMMA on k-cols 0..95
// (2m x 4n layout, warp tile 64x32). Warps 8-15: dp4a on k-cols 96..127
// (8x8 outputs/thread). Partials merged via padded s32 smem in the epilogue.
template<int MODE, int K, int CHN, int NT>
__global__ void __launch_bounds__(512, 1)
k_gemm_hy(const float* __restrict__ bias, float* __restrict__ out2)
{
    extern __shared__ int8_t smem[];
    const uint32_t sbase = s2u(smem);
    const int tid = threadIdx.x, wid = tid >> 5, lane = tid & 31;
    const int mt = blockIdx.x / NT, nt = blockIdx.x % NT;
    const int m0 = mt * 128, n0 = nt * 128;
    constexpr int NS = (MODE == 1) ? FDIM : DDIM;

    const int8_t* Ag = (MODE == 1) ? g_qx : g_qh;
    const int8_t* Bg = (MODE == 1) ? g_w1 : g_w2;

    // loader mapping: each thread stages 2 A-chunks + 2 B-chunks of 16B
    const int lr = tid >> 2;            // row 0..127
    const int lc0 = (tid & 3) * 2;      // chunk 0,2,4,6
    const int8_t* aro = Ag + (size_t)(m0 + lr) * K;
    const int8_t* bro = Bg + (size_t)(n0 + lr) * K;

#define LOAD_CHUNK(kt) do {                                                     \
    uint32_t _b = sbase + (uint32_t)(((kt) & 3) * 32768);                       \
    int _k0 = (kt) * 128;                                                       \
    _Pragma("unroll")                                                           \
    for (int _u = 0; _u < 2; _u++) {                                            \
        int _c = lc0 + _u;                                                      \
        uint32_t _so = (uint32_t)(lr * 128) + (SW(lr, _c) << 4);                \
        cp16(_b + _so,          aro + _k0 + _c * 16);                           \
        cp16(_b + 16384u + _so, bro + _k0 + _c * 16);                           \
    }                                                                           \
    asm volatile("cp.async.commit_group;" ::: "memory");                        \
} while (0)

    // tensor-warp state
    const int wm = (wid >> 2) * 64, wn = (wid & 3) * 32;
    int d[4][4][4];
    // dp4a-warp state
    const int dtid = tid - 256;
    const int tr = dtid >> 4, tc = dtid & 15;   // 16x16 thread grid of 8x8 blocks
    int dd[8][8];

    if (tid < 256) {
#pragma unroll
        for (int mi = 0; mi < 4; mi++)
#pragma unroll
            for (int ni = 0; ni < 4; ni++)
#pragma unroll
                for (int e = 0; e < 4; e++) d[mi][ni][e] = 0;
    } else {
#pragma unroll
        for (int i = 0; i < 8; i++)
#pragma unroll
            for (int j = 0; j < 8; j++) dd[i][j] = 0;
    }

    LOAD_CHUNK(0);
    LOAD_CHUNK(1);
    LOAD_CHUNK(2);

    for (int kt = 0; kt < CHN; kt++) {
        asm volatile("cp.async.wait_group 2;" ::: "memory");
        __syncthreads();
        if (kt + 3 < CHN) LOAD_CHUNK(kt + 3);
        else asm volatile("cp.async.commit_group;" ::: "memory");

        const uint32_t ab = sbase + (uint32_t)((kt & 3) * 32768);
        const uint32_t bb = ab + 16384u;

        if (tid < 256) {
            // ---- IMMA on k-cols 0..95 (chunks 0..5) ----
#pragma unroll
            for (int kc = 0; kc < 3; kc++) {
                uint32_t afr[4][4], bfr[2][4];
#pragma unroll
                for (int mi = 0; mi < 4; mi++) {
                    int row = wm + mi * 16 + (lane & 7) + ((lane >> 3) & 1) * 8;
                    int c = 2 * kc + (lane >> 4);
                    ldm_x4(afr[mi], ab + (uint32_t)(row * 128) + (SW(row, c) << 4));
                }
#pragma unroll
                for (int np = 0; np < 2; np++) {
                    int n = wn + np * 16 + ((lane >> 4) << 3) + (lane & 7);
                    int c = 2 * kc + ((lane >> 3) & 1);
                    ldm_x4(bfr[np], bb + (uint32_t)(n * 128) + (SW(n, c) << 4));
                }
#pragma unroll
                for (int mi = 0; mi < 4; mi++)
#pragma unroll
                    for (int ni = 0; ni < 4; ni++)
                        imma(d[mi][ni], afr[mi], bfr[ni >> 1] + (ni & 1) * 2);
            }
        } else {
            // ---- dp4a on k-cols 96..127 (chunks 6,7) ----
#pragma unroll
            for (int ch = 6; ch < 8; ch++) {
                uint4 a16[8];
#pragma unroll
                for (int i = 0; i < 8; i++) {
                    int r = tr * 8 + i;
                    a16[i] = *(const uint4*)(smem + ((kt & 3) * 32768) +
                                             r * 128 + (SW(r, ch) << 4));
                }
#pragma unroll
                for (int j = 0; j < 8; j++) {
                    int r = tc * 8 + j;
                    uint4 b16 = *(const uint4*)(smem + ((kt & 3) * 32768) + 16384 +
                                                r * 128 + (SW(r, ch) << 4));
#pragma unroll
                    for (int i = 0; i < 8; i++) {
                        dd[i][j] = dp4a_((int)a16[i].x, (int)b16.x, dd[i][j]);
                        dd[i][j] = dp4a_((int)a16[i].y, (int)b16.y, dd[i][j]);
                        dd[i][j] = dp4a_((int)a16[i].z, (int)b16.z, dd[i][j]);
                        dd[i][j] = dp4a_((int)a16[i].w, (int)b16.w, dd[i][j]);
                    }
                }
            }
        }
    }

    // ---------------- epilogue: merge + scale + store ----------------
    asm volatile("cp.async.wait_group 0;" ::: "memory");
    __syncthreads();

    int* epi = (int*)smem;   // [128][132] padded s32
    if (tid < 256) {
#pragma unroll
        for (int mi = 0; mi < 4; mi++) {
            int rlo = wm + mi * 16 + (lane >> 2);
#pragma unroll
            for (int ni = 0; ni < 4; ni++) {
                int col = wn + ni * 8 + 2 * (lane & 3);
                *(int2*)(epi + rlo * 132 + col)       = make_int2(d[mi][ni][0], d[mi][ni][1]);
                *(int2*)(epi + (rlo + 8) * 132 + col) = make_int2(d[mi][ni][2], d[mi][ni][3]);
            }
        }
    }
    __syncthreads();

    if (tid >= 256) {
        const float wf = g_wmeta[(MODE == 1) ? 1 : 3];
        const float* scp = (MODE == 1) ? g_ascale : g_hscale;
        float* outp = ((MODE == 1) ? g_hidden : out2);
        float4 b0 = *(const float4*)(bias + n0 + tc * 8);
        float4 b1 = *(const float4*)(bias + n0 + tc * 8 + 4);
#pragma unroll
        for (int i = 0; i < 8; i++) {
            int row = tr * 8 + i;
            float s = scp[m0 + row] * wf;
            const int* er = epi + row * 132 + tc * 8;
            float4 v0, v1;
            v0.x = (float)(er[0] + dd[i][0]) * s + b0.x;
            v0.y = (float)(er[1] + dd[i][1]) * s + b0.y;
            v0.z = (float)(er[2] + dd[i][2]) * s + b0.z;
            v0.w = (float)(er[3] + dd[i][3]) * s + b0.w;
            v1.x = (float)(er[4] + dd[i][4]) * s + b1.x;
            v1.y = (float)(er[5] + dd[i][5]) * s + b1.y;
            v1.z = (float)(er[6] + dd[i][6]) * s + b1.z;
            v1.w = (float)(er[7] + dd[i][7]) * s + b1.w;
            if (MODE == 1) {
                v0.x = fmaxf(v0.x, 0.f); v0.x *= v0.x;
                v0.y = fmaxf(v0.y, 0.f); v0.y *= v0.y;
                v0.z = fmaxf(v0.z, 0.f); v0.z *= v0.z;
                v0.w = fmaxf(v0.w, 0.f); v0.w *= v0.w;
                v1.x = fmaxf(v1.x, 0.f); v1.x *= v1.x;
                v1.y = fmaxf(v1.y, 0.f); v1.y *= v1.y;
                v1.z = fmaxf(v1.z, 0.f); v1.z *= v1.z;
                v1.w = fmaxf(v1.w, 0.f); v1.w *= v1.w;
            }
            float* orow = outp + (size_t)(m0 + row) * NS + n0 + tc * 8;
            *(float4*)orow = v0;
            *(float4*)(orow + 4) = v1;
        }
    }
}

#define SMEM_HY 131072

// ---------------- launch ----------------
extern "C" void kernel_launch(void* const* d_in, const int* in_sizes, int n_in,
                              void* d_out, int out_size) {
    (void)in_sizes; (void)n_in; (void)out_size;
    const float* x      = (const float*)d_in[0];
    const float* up_w   = (const float*)d_in[1];
    const float* up_b   = (const float*)d_in[2];
    const float* down_w = (const float*)d_in[3];
    const float* down_b = (const float*)d_in[4];
    float* out = (float*)d_out;

    cudaFuncSetAttribute(k_gemm_hy<1, DDIM, 8, 24>,
                         cudaFuncAttributeMaxDynamicSharedMemorySize, SMEM_HY);
    cudaFuncSetAttribute(k_gemm_hy<2, FDIM, 24, 8>,
                         cudaFuncAttributeMaxDynamicSharedMemorySize, SMEM_HY);

    k_quant_x<<<MTOK, 256>>>(x);                    // 1
    k_wsum<<<2048, 256>>>(up_w, down_w);            // 2
    k_ternarize<<<6144, 256>>>(up_w, down_w);       // 3
    // GEMM1: M=32768, N=3072, K=1024 -> relu^2 into g_hidden
    k_gemm_hy<1, DDIM, 8, 24><<<256 * 24, 512, SMEM_HY>>>(up_b, nullptr);   // 4
    k_quant_h<<<MTOK, 256>>>();                     // 5
    // GEMM2: M=32768, N=1024, K=3072 -> out with bias
    k_gemm_hy<2, FDIM, 24, 8><<<256 * 8, 512, SMEM_HY>>>(down_b, out);      // 6
}

// round 14
// speedup vs baseline: 1.6627x; 1.6627x over previous
#include <cuda_runtime.h>
#include <cuda_bf16.h>
#include <stdint.h>

#define EPSQ 1e-5f
#define MTOK 32768
#define DDIM 1024
#define FDIM 3072

// ---------------- scratch (__device__ globals; no allocation) ----------------
__device__ int8_t g_qx[(size_t)MTOK * DDIM];        // 32 MB
__device__ int8_t g_qh[(size_t)MTOK * FDIM];        // 96 MB
__device__ int8_t g_w1[(size_t)FDIM * DDIM];        // 3 MB
__device__ int8_t g_w2[(size_t)DDIM * FDIM];        // 3 MB
__device__ float  g_hidden[(size_t)MTOK * FDIM];    // 384 MB
__device__ float  g_ascale[MTOK];
__device__ float  g_hscale[MTOK];
__device__ float  g_wpart[2048];
__device__ float  g_wmeta[4];  // ws1, fac1, ws2, fac2

// ---------------- ptx helpers (base sm_80+ ISA only) ----------------
__device__ __forceinline__ uint32_t s2u(const void* p) {
    uint32_t a;
    asm("{ .reg .u64 t; cvta.to.shared.u64 t, %1; cvt.u32.u64 %0, t; }" : "=r"(a) : "l"(p));
    return a;
}
__device__ __forceinline__ void cp16(uint32_t saddr, const void* gaddr) {
    asm volatile("cp.async.cg.shared.global [%0], [%1], 16;" :: "r"(saddr), "l"(gaddr) : "memory");
}
__device__ __forceinline__ void ldm_x4(uint32_t* r, uint32_t addr) {
    asm volatile("ldmatrix.sync.aligned.m8n8.x4.shared.b16 {%0,%1,%2,%3}, [%4];"
                 : "=r"(r[0]), "=r"(r[1]), "=r"(r[2]), "=r"(r[3]) : "r"(addr));
}
__device__ __forceinline__ void imma(int* d, const uint32_t* a, const uint32_t* b) {
    asm volatile(
        "mma.sync.aligned.m16n8k32.row.col.s32.s8.s8.s32 "
        "{%0,%1,%2,%3}, {%4,%5,%6,%7}, {%8,%9}, {%0,%1,%2,%3};"
        : "+r"(d[0]), "+r"(d[1]), "+r"(d[2]), "+r"(d[3])
        : "r"(a[0]), "r"(a[1]), "r"(a[2]), "r"(a[3]), "r"(b[0]), "r"(b[1]));
}

// ---------------- activation quantization (x) ----------------
__global__ void k_quant_x(const float* __restrict__ x) {
    int m = blockIdx.x, t = threadIdx.x;  // 256 threads, row of 1024
    const float4* row = (const float4*)(x + (size_t)m * DDIM);
    float4 v = row[t];
    float am = fmaxf(fmaxf(fabsf(v.x), fabsf(v.y)), fmaxf(fabsf(v.z), fabsf(v.w)));
    for (int o = 16; o > 0; o >>= 1) am = fmaxf(am, __shfl_xor_sync(0xffffffffu, am, o));
    __shared__ float red[8];
    __shared__ float s_c;
    if ((t & 31) == 0) red[t >> 5] = am;
    __syncthreads();
    if (t == 0) {
        float c = red[0];
        for (int i = 1; i < 8; i++) c = fmaxf(c, red[i]);
        c = fmaxf(c, EPSQ);
        s_c = c;
        g_ascale[m] = c / 127.0f;
    }
    __syncthreads();
    float scale = 127.0f / s_c;
    char4 q;
    q.x = (signed char)fminf(fmaxf(rintf(v.x * scale), -128.f), 127.f);
    q.y = (signed char)fminf(fmaxf(rintf(v.y * scale), -128.f), 127.f);
    q.z = (signed char)fminf(fmaxf(rintf(v.z * scale), -128.f), 127.f);
    q.w = (signed char)fminf(fmaxf(rintf(v.w * scale), -128.f), 127.f);
    *(char4*)(g_qx + (size_t)m * DDIM + t * 4) = q;
}

// ---------------- weight |w| partial sums ----------------
__global__ void k_wsum(const float* __restrict__ up_w, const float* __restrict__ down_w) {
    int b = blockIdx.x, t = threadIdx.x;
    const float* base = (b < 1024) ? (up_w + (size_t)b * 3072)
                                   : (down_w + (size_t)(b - 1024) * 3072);
    const float4* v4 = (const float4*)base;
    float s = 0.f;
#pragma unroll
    for (int j = 0; j < 3; j++) {
        float4 v = v4[t + j * 256];
        s += fabsf(v.x) + fabsf(v.y) + fabsf(v.z) + fabsf(v.w);
    }
    for (int o = 16; o > 0; o >>= 1) s += __shfl_down_sync(0xffffffffu, s, o);
    __shared__ float red[8];
    if ((t & 31) == 0) red[t >> 5] = s;
    __syncthreads();
    if (t == 0) {
        float tot = 0.f;
        for (int i = 0; i < 8; i++) tot += red[i];
        g_wpart[b] = tot;
    }
}

// ---------------- ternarize (scale computed redundantly per block, fixed order) ----
__global__ void k_ternarize(const float* __restrict__ up_w, const float* __restrict__ down_w) {
    int t = threadIdx.x;  // 256
    float s1 = 0.f, s2 = 0.f;
#pragma unroll
    for (int j = 0; j < 4; j++) {
        s1 += g_wpart[t + j * 256];
        s2 += g_wpart[1024 + t + j * 256];
    }
    for (int o = 16; o > 0; o >>= 1) {
        s1 += __shfl_down_sync(0xffffffffu, s1, o);
        s2 += __shfl_down_sync(0xffffffffu, s2, o);
    }
    __shared__ float r1[8], r2[8];
    __shared__ float sws[2];
    if ((t & 31) == 0) { r1[t >> 5] = s1; r2[t >> 5] = s2; }
    __syncthreads();
    if (t == 0) {
        float t1 = 0.f, t2 = 0.f;
        for (int i = 0; i < 8; i++) { t1 += r1[i]; t2 += r2[i]; }
        float m1 = t1 / (3072.0f * 1024.0f);
        float m2 = t2 / (3072.0f * 1024.0f);
        float f1 = fmaxf(m1, EPSQ), f2 = fmaxf(m2, EPSQ);
        sws[0] = 1.0f / f1;
        sws[1] = 1.0f / f2;
        if (blockIdx.x == 0) {
            g_wmeta[0] = 1.0f / f1; g_wmeta[1] = f1;
            g_wmeta[2] = 1.0f / f2; g_wmeta[3] = f2;
        }
    }
    __syncthreads();

    const size_t half = (size_t)3072 * 1024;
    size_t i = ((size_t)blockIdx.x * 256 + t) * 4;
    const float* src;
    int8_t* dst;
    float ws;
    if (i < half) { src = up_w + i;            dst = g_w1 + i;          ws = sws[0]; }
    else          { src = down_w + (i - half); dst = g_w2 + (i - half); ws = sws[1]; }
    float4 w = *(const float4*)src;
    char4 q;
    q.x = (signed char)fminf(fmaxf(rintf(w.x * ws), -1.f), 1.f);
    q.y = (signed char)fminf(fmaxf(rintf(w.y * ws), -1.f), 1.f);
    q.z = (signed char)fminf(fmaxf(rintf(w.z * ws), -1.f), 1.f);
    q.w = (signed char)fminf(fmaxf(rintf(w.w * ws), -1.f), 1.f);
    *(char4*)dst = q;
}

// ---------------- activation quantization (hidden) ----------------
__global__ void k_quant_h() {
    int m = blockIdx.x, t = threadIdx.x;  // 256 threads, row of 3072
    const float4* row = (const float4*)(g_hidden + (size_t)m * FDIM);
    float4 v[3];
    float am = 0.f;
#pragma unroll
    for (int j = 0; j < 3; j++) {
        v[j] = row[t + j * 256];
        am = fmaxf(am, fmaxf(fmaxf(fabsf(v[j].x), fabsf(v[j].y)),
                             fmaxf(fabsf(v[j].z), fabsf(v[j].w))));
    }
    for (int o = 16; o > 0; o >>= 1) am = fmaxf(am, __shfl_xor_sync(0xffffffffu, am, o));
    __shared__ float red[8];
    __shared__ float s_c;
    if ((t & 31) == 0) red[t >> 5] = am;
    __syncthreads();
    if (t == 0) {
        float c = red[0];
        for (int i = 1; i < 8; i++) c = fmaxf(c, red[i]);
        c = fmaxf(c, EPSQ);
        s_c = c;
        g_hscale[m] = c / 127.0f;
    }
    __syncthreads();
    float scale = 127.0f / s_c;
#pragma unroll
    for (int j = 0; j < 3; j++) {
        char4 q;
        q.x = (signed char)fminf(fmaxf(rintf(v[j].x * scale), -128.f), 127.f);
        q.y = (signed char)fminf(fmaxf(rintf(v[j].y * scale), -128.f), 127.f);
        q.z = (signed char)fminf(fmaxf(rintf(v[j].z * scale), -128.f), 127.f);
        q.w = (signed char)fminf(fmaxf(rintf(v[j].w * scale), -128.f), 127.f);
        *(char4*)(g_qh + (size_t)m * FDIM + (t + j * 256) * 4) = q;
    }
}

// ---------------- int8 tensor-core GEMM, 128x128 tile, K-step 64, 3-stage ----
// 256 threads = 8 warps in 2(m) x 4(n); warp tile 64x32. 3-stage cp.async
// ring (16KB/stage), ONE __syncthreads per K-step. Smem rows of 64B, chunk
// swizzle c ^ ((r>>1)&3) (conflict-free for stores and all ldmatrix phases).
__global__ void __launch_bounds__(256, 2)
k_gemm(const float* __restrict__ bias, float* __restrict__ out2,
       int N, int K, int KT, int NT, int mode)
{
    __shared__ int8_t smem[3][16384];  // per stage: A[128][64] then B[128][64]
    const uint32_t sbase = s2u(smem);
    int tid = threadIdx.x, wid = tid >> 5, lane = tid & 31;
    int mt = blockIdx.x / NT, nt = blockIdx.x % NT;
    int m0 = mt * 128, n0 = nt * 128;
    int wm = (wid >> 2) * 64, wn = (wid & 3) * 32;

    const int8_t* A = (mode == 1) ? g_qx : g_qh;
    const int8_t* B = (mode == 1) ? g_w1 : g_w2;

    const int chr = tid >> 2;   // load row (0..63)
    const int chc = tid & 3;    // 16B chunk (0..3)

    int d[4][4][4];
#pragma unroll
    for (int mi = 0; mi < 4; mi++)
#pragma unroll
        for (int ni = 0; ni < 4; ni++)
#pragma unroll
            for (int e = 0; e < 4; e++) d[mi][ni][e] = 0;

#define LOAD_TILE(kt, buf) do {                                                  \
    int _k0 = (kt) * 64;                                                         \
    uint32_t _b = sbase + (uint32_t)(buf) * 16384u;                              \
    _Pragma("unroll")                                                            \
    for (int _j = 0; _j < 2; _j++) {                                             \
        int _r = chr + _j * 64;                                                  \
        uint32_t _so = (uint32_t)(_r * 64 + ((chc ^ ((_r >> 1) & 3)) << 4));     \
        cp16(_b + _so,         A + (size_t)(m0 + _r) * K + _k0 + chc * 16);      \
        cp16(_b + 8192u + _so, B + (size_t)(n0 + _r) * K + _k0 + chc * 16);      \
    }                                                                            \
    asm volatile("cp.async.commit_group;" ::: "memory");                         \
} while (0)

    LOAD_TILE(0, 0);
    LOAD_TILE(1, 1);

    int buf = 0;
    for (int kt = 0; kt < KT; kt++) {
        if (kt < KT - 1) asm volatile("cp.async.wait_group 1;" ::: "memory");
        else             asm volatile("cp.async.wait_group 0;" ::: "memory");
        __syncthreads();
        if (kt + 2 < KT) {
            int nb = buf + 2; if (nb >= 3) nb -= 3;
            LOAD_TILE(kt + 2, nb);
        }

        uint32_t ab = sbase + (uint32_t)buf * 16384u;
        uint32_t bb = ab + 8192u;
#pragma unroll
        for (int kc = 0; kc < 2; kc++) {
            uint32_t afr[4][4], bfr[2][4];
#pragma unroll
            for (int mi = 0; mi < 4; mi++) {
                int row = wm + mi * 16 + (lane & 7) + ((lane >> 3) & 1) * 8;
                int chunk = 2 * kc + (lane >> 4);
                ldm_x4(afr[mi], ab + (uint32_t)(row * 64 + ((chunk ^ ((row >> 1) & 3)) << 4)));
            }
#pragma unroll
            for (int np = 0; np < 2; np++) {
                int n = wn + np * 16 + ((lane >> 4) << 3) + (lane & 7);
                int chunk = 2 * kc + ((lane >> 3) & 1);
                ldm_x4(bfr[np], bb + (uint32_t)(n * 64 + ((chunk ^ ((n >> 1) & 3)) << 4)));
            }
#pragma unroll
            for (int mi = 0; mi < 4; mi++)
#pragma unroll
                for (int ni = 0; ni < 4; ni++)
                    imma(d[mi][ni], afr[mi], bfr[ni >> 1] + (ni & 1) * 2);
        }
        if (++buf == 3) buf = 0;
    }

    // ---------------- epilogue ----------------
    const float wf = g_wmeta[(mode == 1) ? 1 : 3];
    const float* sc = (mode == 1) ? g_ascale : g_hscale;
    float* outp = (mode == 1) ? g_hidden : out2;

#pragma unroll
    for (int mi = 0; mi < 4; mi++) {
        int mlo = m0 + wm + mi * 16 + (lane >> 2);
        float slo = sc[mlo] * wf;
        float shi = sc[mlo + 8] * wf;
        float* rlo = outp + (size_t)mlo * N;
        float* rhi = outp + (size_t)(mlo + 8) * N;
#pragma unroll
        for (int ni = 0; ni < 4; ni++) {
            int n = n0 + wn + ni * 8 + 2 * (lane & 3);
            float2 bv = *(const float2*)(bias + n);
            float2 v0, v1;
            v0.x = (float)d[mi][ni][0] * slo + bv.x;
            v0.y = (float)d[mi][ni][1] * slo + bv.y;
            v1.x = (float)d[mi][ni][2] * shi + bv.x;
            v1.y = (float)d[mi][ni][3] * shi + bv.y;
            if (mode == 1) {
                v0.x = fmaxf(v0.x, 0.f); v0.x *= v0.x;
                v0.y = fmaxf(v0.y, 0.f); v0.y *= v0.y;
                v1.x = fmaxf(v1.x, 0.f); v1.x *= v1.x;
                v1.y = fmaxf(v1.y, 0.f); v1.y *= v1.y;
            }
            *(float2*)(rlo + n) = v0;
            *(float2*)(rhi + n) = v1;
        }
    }
}

// ---------------- launch ----------------
extern "C" void kernel_launch(void* const* d_in, const int* in_sizes, int n_in,
                              void* d_out, int out_size) {
    (void)in_sizes; (void)n_in; (void)out_size;
    const float* x      = (const float*)d_in[0];
    const float* up_w   = (const float*)d_in[1];
    const float* up_b   = (const float*)d_in[2];
    const float* down_w = (const float*)d_in[3];
    const float* down_b = (const float*)d_in[4];
    float* out = (float*)d_out;

    k_quant_x<<<MTOK, 256>>>(x);                    // 1
    k_wsum<<<2048, 256>>>(up_w, down_w);            // 2
    k_ternarize<<<6144, 256>>>(up_w, down_w);       // 3 (fused scale reduce)
    // GEMM1: M=32768, N=3072, K=1024 -> relu^2 into g_hidden
    k_gemm<<<256 * 24, 256>>>(up_b, nullptr, FDIM, DDIM, DDIM / 64, 24, 1);  // 4
    k_quant_h<<<MTOK, 256>>>();                     // 5
    // GEMM2: M=32768, N=1024, K=3072 -> out with bias
    k_gemm<<<256 * 8, 256>>>(down_b, out, DDIM, FDIM, FDIM / 64, 8, 2);      // 6
}